// round 7
// baseline (speedup 1.0000x reference)
#include <cuda_runtime.h>

#define RPB 128   // rows per block
#define TPB 192   // 128 math threads + uniform 1-float4/thread epilogue

__device__ __forceinline__ float fsqrt_ap(float x) {
    float r; asm("sqrt.approx.f32 %0, %1;" : "=f"(r) : "f"(x)); return r;
}
__device__ __forceinline__ float frsqrt_ap(float x) {
    float r; asm("rsqrt.approx.f32 %0, %1;" : "=f"(r) : "f"(x)); return r;
}
__device__ __forceinline__ float frcp_ap(float x) {
    float r; asm("rcp.approx.f32 %0, %1;" : "=f"(r) : "f"(x)); return r;
}

__global__ __launch_bounds__(TPB, 7) void vp_lattice_kernel(
    const float* __restrict__ lt_g,
    const float* __restrict__ l0_g,
    const float* __restrict__ pl_g,
    const float* __restrict__ alpha_bars,
    const float* __restrict__ betas,
    const float* __restrict__ sigmas,
    const float* __restrict__ zn_g,
    const int*   __restrict__ traw,
    float* __restrict__ out_g,
    int B)
{
    // s_pl doubles as vec storage after the math phase (row slot reuse).
    __shared__ float s_pl   [RPB * 9];
    __shared__ float s_coef [RPB];
    __shared__ float s_scale[RPB];
    __shared__ float s_zm   [RPB];

    const int tid = threadIdx.x;
    const long long base = (long long)blockIdx.x * RPB;
    const int nrows = (int)min((long long)RPB, (long long)B - base);
    const bool full = (nrows == RPB);

    // ---- t dtype detection, per-thread (uniform addrs -> L1 broadcast) ----
    const int acc = traw[1] | traw[3] | traw[5] | traw[7] |
                    traw[9] | traw[11] | traw[13] | traw[15];
    const int tstride = (acc == 0) ? 2 : 1;

    // ---- stage pred_lattice into smem (288 float4 over 192 threads) ----
    if (full) {
        const float4* pl4 = (const float4*)(pl_g + base * 9);
        #pragma unroll
        for (int i = tid; i < RPB * 9 / 4; i += TPB)
            ((float4*)s_pl)[i] = __ldcs(&pl4[i]);
    } else {
        for (int i = tid; i < nrows * 9; i += TPB)
            s_pl[i] = pl_g[base * 9 + i];
    }

    // ---- t + schedule gathers for math threads (issued during staging) ----
    int   tt = 0;
    float beta_t = 0.f, albar = 0.f, sigma = 0.f;
    const bool mth = (tid < nrows);
    if (mth) {
        tt     = __ldg(&traw[(base + tid) * tstride]);
        beta_t = __ldg(&betas[tt]);
        albar  = __ldg(&alpha_bars[tt]);
        sigma  = __ldg(&sigmas[tt]);
    }
    const float beta_m2 = __ldg(&betas[999]);   // betas[-2], len 1001

    // ---- PREFETCH epilogue streams (independent of math; 3 LDG.128/thread
    //      stay in flight across the entire math phase) ----
    float4 pa, pb, pz;
    if (full) {
        pa = __ldcs((const float4*)(lt_g + base * 6) + tid);
        pb = __ldcs((const float4*)(l0_g + base * 6) + tid);
        pz = __ldcs((const float4*)(zn_g + base * 6) + tid);
    }
    __syncthreads();

    // ---- per-row math (threads 0..127) ----
    if (mth) {
        const int row = tid;
        const float alpha = fmaxf(1.0f - beta_t, 1.0f - beta_m2);

        const float a0 = s_pl[row*9+0], a1 = s_pl[row*9+1], a2 = s_pl[row*9+2];
        const float a3 = s_pl[row*9+3], a4 = s_pl[row*9+4], a5 = s_pl[row*9+5];
        const float a6 = s_pl[row*9+6], a7 = s_pl[row*9+7], a8 = s_pl[row*9+8];

        // M = A^T A
        const float m00 = a0*a0 + a3*a3 + a6*a6;
        const float m11 = a1*a1 + a4*a4 + a7*a7;
        const float m22 = a2*a2 + a5*a5 + a8*a8;
        const float m01 = a0*a1 + a3*a4 + a6*a7;
        const float m02 = a0*a2 + a3*a5 + a6*a8;
        const float m12 = a1*a2 + a4*a5 + a7*a8;

        // invariants
        const float e1 = m00 + m11 + m22;
        const float e2 = (m00*m11 - m01*m01)
                       + (m00*m22 - m02*m02)
                       + (m11*m22 - m12*m12);
        const float e3 = m00*(m11*m22 - m12*m12)
                       - m01*(m01*m22 - m12*m02)
                       + m02*(m01*m12 - m11*m02);

        // elementary symmetric functions of singular values (fixed point,
        // loop gain <= 1/9 by AM-GM)
        const float sc  = fsqrt_ap(fmaxf(e3, 0.0f));
        const float e2c = fmaxf(e2, 0.0f);
        float sb = fsqrt_ap(e2c);
        float sa = fsqrt_ap(fmaxf(e1 + 2.0f * sb, 0.0f));
        #pragma unroll
        for (int it = 0; it < 4; it++) {
            sb = fsqrt_ap(fmaxf(e2c + 2.0f * sc * sa, 0.0f));
            sa = fsqrt_ap(fmaxf(e1 + 2.0f * sb, 0.0f));
        }

        // U = sqrt(M) = sa*I + k*adj(M + sb I)
        const float n00 = m00 + sb, n11 = m11 + sb, n22 = m22 + sb;
        const float c00 = n11*n22 - m12*m12;
        const float c01 = m02*m12 - m01*n22;
        const float c02 = m01*m12 - n11*m02;
        const float c11 = n00*n22 - m02*m02;
        const float c12 = m01*m02 - n00*m12;
        const float c22 = n00*n11 - m01*m01;
        const float det = fmaxf(n00*c00 + m01*c01 + m02*c02, 1e-30f);
        const float k   = (sc - sa * sb) * frcp_ap(det);

        s_pl[row*9+0] = sa + k * c00;
        s_pl[row*9+1] =      k * c01;
        s_pl[row*9+2] =      k * c02;
        s_pl[row*9+3] = sa + k * c11;
        s_pl[row*9+4] =      k * c12;
        s_pl[row*9+5] = sa + k * c22;

        s_coef [row] = frsqrt_ap(alpha + 1e-8f);
        s_scale[row] = (1.0f - alpha) * frsqrt_ap(1.0f - albar + 1e-8f);
        s_zm   [row] = (tt > 1) ? sigma : 0.0f;
    }
    __syncthreads();

    // ---- epilogue: exactly 1 float4/thread/array, inputs already in regs ----
    if (full) {
        const float av[4] = { pa.x, pa.y, pa.z, pa.w };
        const float bv[4] = { pb.x, pb.y, pb.z, pb.w };
        const float zv[4] = { pz.x, pz.y, pz.z, pz.w };
        float ov[4];
        const int e0 = tid * 4;
        #pragma unroll
        for (int c = 0; c < 4; c++) {
            const int e = e0 + c;
            const int row = e / 6;
            const int kk  = e - row * 6;
            const float v  = s_pl[row*9 + kk];     // aliased vec
            const float pn = av[c] - 0.5f * (v + bv[c]);
            ov[c] = s_coef[row] * (av[c] - s_scale[row] * pn)
                  + s_zm[row] * zv[c];
        }
        __stcs((float4*)(out_g + base * 6) + tid,
               make_float4(ov[0], ov[1], ov[2], ov[3]));
    } else {
        for (int i = tid; i < nrows * 6; i += TPB) {
            const int row = i / 6;
            const int kk  = i - row * 6;
            const float ltv = lt_g[base*6 + i];
            const float pn  = ltv - 0.5f * (s_pl[row*9+kk] + l0_g[base*6 + i]);
            out_g[base*6 + i] = s_coef[row] * (ltv - s_scale[row] * pn)
                              + s_zm[row] * zn_g[base*6 + i];
        }
    }
}

extern "C" void kernel_launch(void* const* d_in, const int* in_sizes, int n_in,
                              void* d_out, int out_size)
{
    const float* lt  = (const float*)d_in[0];
    const float* l0  = (const float*)d_in[1];
    const float* pl  = (const float*)d_in[2];
    const float* ab  = (const float*)d_in[3];
    const float* be  = (const float*)d_in[4];
    const float* si  = (const float*)d_in[5];
    const float* zn  = (const float*)d_in[6];
    const int*   t   = (const int*)d_in[7];
    float* out = (float*)d_out;

    const int B = in_sizes[0] / 6;          // lt is (B, 6)
    const int blocks = (B + RPB - 1) / RPB;

    vp_lattice_kernel<<<blocks, TPB>>>(lt, l0, pl, ab, be, si, zn, t, out, B);
}

// round 8
// speedup vs baseline: 1.0822x; 1.0822x over previous
#include <cuda_runtime.h>

#define RPB 64   // rows per block
#define TPB 64   // 1 row per thread, 2 warps per CTA, up to 32 CTAs/SM

__device__ __forceinline__ float fsqrt_ap(float x) {
    float r; asm("sqrt.approx.f32 %0, %1;" : "=f"(r) : "f"(x)); return r;
}
__device__ __forceinline__ float frsqrt_ap(float x) {
    float r; asm("rsqrt.approx.f32 %0, %1;" : "=f"(r) : "f"(x)); return r;
}
__device__ __forceinline__ float frcp_ap(float x) {
    float r; asm("rcp.approx.f32 %0, %1;" : "=f"(r) : "f"(x)); return r;
}

__global__ __launch_bounds__(TPB, 32) void vp_lattice_kernel(
    const float* __restrict__ lt_g,
    const float* __restrict__ l0_g,
    const float* __restrict__ pl_g,
    const float* __restrict__ alpha_bars,
    const float* __restrict__ betas,
    const float* __restrict__ sigmas,
    const float* __restrict__ zn_g,
    const int*   __restrict__ traw,
    float* __restrict__ out_g,
    int B)
{
    // Single smem array. Per 9-float row slot:
    //   before math: the staged 3x3 pred_lattice row
    //   after  math: [0..5] = vec, [6] = coef, [7] = scale, [8] = zmul
    __shared__ float s_pl[RPB * 9];

    const int tid = threadIdx.x;
    const long long base = (long long)blockIdx.x * RPB;
    const int nrows = (int)min((long long)RPB, (long long)B - base);
    const bool full = (nrows == RPB);

    // ---- t dtype detection, per-thread (uniform addrs -> broadcast) ----
    const int acc = traw[1] | traw[3] | traw[5] | traw[7] |
                    traw[9] | traw[11] | traw[13] | traw[15];
    const int tstride = (acc == 0) ? 2 : 1;

    // ---- stage pred_lattice (144 float4 over 64 threads) ----
    if (full) {
        const float4* pl4 = (const float4*)(pl_g + base * 9);
        #pragma unroll
        for (int i = tid; i < RPB * 9 / 4; i += TPB)
            ((float4*)s_pl)[i] = __ldcs(&pl4[i]);
    } else {
        for (int i = tid; i < nrows * 9; i += TPB)
            s_pl[i] = pl_g[base * 9 + i];
    }
    __syncthreads();

    if (tid < nrows) {
        const int row = tid;
        const int tt = __ldg(&traw[(base + row) * tstride]);

        const float beta_t  = __ldg(&betas[tt]);
        const float beta_m2 = __ldg(&betas[999]);          // betas[-2], len 1001
        const float alpha   = fmaxf(1.0f - beta_t, 1.0f - beta_m2);
        const float albar   = __ldg(&alpha_bars[tt]);
        const float sigma   = __ldg(&sigmas[tt]);

        const float a0 = s_pl[row*9+0], a1 = s_pl[row*9+1], a2 = s_pl[row*9+2];
        const float a3 = s_pl[row*9+3], a4 = s_pl[row*9+4], a5 = s_pl[row*9+5];
        const float a6 = s_pl[row*9+6], a7 = s_pl[row*9+7], a8 = s_pl[row*9+8];

        // M = A^T A (symmetric PSD)
        const float m00 = a0*a0 + a3*a3 + a6*a6;
        const float m11 = a1*a1 + a4*a4 + a7*a7;
        const float m22 = a2*a2 + a5*a5 + a8*a8;
        const float m01 = a0*a1 + a3*a4 + a6*a7;
        const float m02 = a0*a2 + a3*a5 + a6*a8;
        const float m12 = a1*a2 + a4*a5 + a7*a8;

        // invariants
        const float e1 = m00 + m11 + m22;
        const float e2 = (m00*m11 - m01*m01)
                       + (m00*m22 - m02*m02)
                       + (m11*m22 - m12*m12);
        const float e3 = m00*(m11*m22 - m12*m12)
                       - m01*(m01*m22 - m12*m02)
                       + m02*(m01*m12 - m11*m02);

        // elementary symmetric functions of singular values (fixed point,
        // loop gain <= 1/9 by AM-GM)
        const float sc  = fsqrt_ap(fmaxf(e3, 0.0f));
        const float e2c = fmaxf(e2, 0.0f);
        float sb = fsqrt_ap(e2c);
        float sa = fsqrt_ap(fmaxf(e1 + 2.0f * sb, 0.0f));
        #pragma unroll
        for (int it = 0; it < 4; it++) {
            sb = fsqrt_ap(fmaxf(e2c + 2.0f * sc * sa, 0.0f));
            sa = fsqrt_ap(fmaxf(e1 + 2.0f * sb, 0.0f));
        }

        // U = sqrt(M) = sa*I + k*adj(M + sb I), exactly symmetric
        const float n00 = m00 + sb, n11 = m11 + sb, n22 = m22 + sb;
        const float c00 = n11*n22 - m12*m12;
        const float c01 = m02*m12 - m01*n22;
        const float c02 = m01*m12 - n11*m02;
        const float c11 = n00*n22 - m02*m02;
        const float c12 = m01*m02 - n00*m12;
        const float c22 = n00*n11 - m01*m01;
        const float det = fmaxf(n00*c00 + m01*c01 + m02*c02, 1e-30f);
        const float k   = (sc - sa * sb) * frcp_ap(det);

        // overwrite own row slot: vec + params
        s_pl[row*9+0] = sa + k * c00;
        s_pl[row*9+1] =      k * c01;
        s_pl[row*9+2] =      k * c02;
        s_pl[row*9+3] = sa + k * c11;
        s_pl[row*9+4] =      k * c12;
        s_pl[row*9+5] = sa + k * c22;
        s_pl[row*9+6] = frsqrt_ap(alpha + 1e-8f);                      // coef
        s_pl[row*9+7] = (1.0f - alpha) * frsqrt_ap(1.0f - albar + 1e-8f); // scale
        s_pl[row*9+8] = (tt > 1) ? sigma : 0.0f;                       // zmul
    }
    __syncthreads();

    // ---- elementwise epilogue: direct coalesced global I/O ----
    if (full) {
        const float4* lt4 = (const float4*)(lt_g + base * 6);
        const float4* l04 = (const float4*)(l0_g + base * 6);
        const float4* z4  = (const float4*)(zn_g + base * 6);
        float4*       o4  = (float4*)(out_g + base * 6);
        #pragma unroll
        for (int i = tid; i < RPB * 6 / 4; i += TPB) {
            const float4 a  = __ldcs(&lt4[i]);
            const float4 b  = __ldcs(&l04[i]);
            const float4 zz = __ldcs(&z4[i]);
            const float av[4] = { a.x, a.y, a.z, a.w };
            const float bv[4] = { b.x, b.y, b.z, b.w };
            const float zv[4] = { zz.x, zz.y, zz.z, zz.w };
            float ov[4];
            const int e0 = i * 4;
            #pragma unroll
            for (int c = 0; c < 4; c++) {
                const int e = e0 + c;
                const int row = e / 6;
                const int kk  = e - row * 6;
                const float v  = s_pl[row*9 + kk];
                const float pn = av[c] - 0.5f * (v + bv[c]);
                ov[c] = s_pl[row*9+6] * (av[c] - s_pl[row*9+7] * pn)
                      + s_pl[row*9+8] * zv[c];
            }
            __stcs(&o4[i], make_float4(ov[0], ov[1], ov[2], ov[3]));
        }
    } else {
        for (int i = tid; i < nrows * 6; i += TPB) {
            const int row = i / 6;
            const int kk  = i - row * 6;
            const float ltv = lt_g[base*6 + i];
            const float pn  = ltv - 0.5f * (s_pl[row*9+kk] + l0_g[base*6 + i]);
            out_g[base*6 + i] = s_pl[row*9+6] * (ltv - s_pl[row*9+7] * pn)
                              + s_pl[row*9+8] * zn_g[base*6 + i];
        }
    }
}

extern "C" void kernel_launch(void* const* d_in, const int* in_sizes, int n_in,
                              void* d_out, int out_size)
{
    const float* lt  = (const float*)d_in[0];
    const float* l0  = (const float*)d_in[1];
    const float* pl  = (const float*)d_in[2];
    const float* ab  = (const float*)d_in[3];
    const float* be  = (const float*)d_in[4];
    const float* si  = (const float*)d_in[5];
    const float* zn  = (const float*)d_in[6];
    const int*   t   = (const int*)d_in[7];
    float* out = (float*)d_out;

    const int B = in_sizes[0] / 6;          // lt is (B, 6)
    const int blocks = (B + RPB - 1) / RPB;

    vp_lattice_kernel<<<blocks, TPB>>>(lt, l0, pl, ab, be, si, zn, t, out, B);
}